// round 15
// baseline (speedup 1.0000x reference)
#include <cuda_runtime.h>
#include <cuda_fp16.h>
#include <math.h>
#include <stdint.h>

#define NN 100000
#define EE 1600000
#define DD 128
#define KP 68          // padded smem row stride in 32-bit words
#define NCH 4          // pipeline chunks
#define FULLM 0xFFFFFFFFu

// ---------------- device scratch (no allocations allowed) ----------------
__device__ int    g_rowptr[NN + 1];
__device__ int    g_cnt[NN];          // zero-init; re-zeroed by scan
__device__ int    g_cursor[NN];
__device__ float  g_dinv[NN];
__device__ int2   g_cedge[EE];        // (src, dinv[src] bits), grouped by dst
__device__ volatile int g_sstat[128]; // lookback status: 0 none, 2 prefix done
__device__ int    g_sagg[128];        // block aggregates
__device__ int    g_spref[128];       // block inclusive prefixes
__device__ __half g_x16[(size_t)NN * DD];  // fp16 copy of input x
__device__ __half g_ax[(size_t)NN * DD];   // aggregated rows (both layers)
__device__ __half g_f16[(size_t)NN * DD];  // layer-1 activations f

// ---------------- edge dtype detection (per warp) ----------------
__device__ __forceinline__ int detect64(const int* __restrict__ eb) {
    unsigned nz = 0;
#pragma unroll
    for (int i = (threadIdx.x & 31); i < 128; i += 32)
        nz |= (eb[2 * i + 1] != 0);
    return __ballot_sync(FULLM, nz) == 0;
}

// ---------------- launch 1: fused x->fp16 convert + degree histogram ------
// blocks [0, cvtB): convert x; blocks [cvtB, cvtB+histB): histogram dst.
// block cvtB+histB-1's thread 0..127 also zero the scan statuses.
__global__ void k_histcvt(const float* __restrict__ x, int total8,
                          const int* __restrict__ eb, int e, int cvtB) {
    int b = blockIdx.x;
    if (b < cvtB) {
        int i = b * blockDim.x + threadIdx.x;
        if (i >= total8) return;
        const float4* x4 = (const float4*)x;
        float4 a = x4[i * 2], c = x4[i * 2 + 1];
        __half2 h0 = __floats2half2_rn(a.x, a.y);
        __half2 h1 = __floats2half2_rn(a.z, a.w);
        __half2 h2 = __floats2half2_rn(c.x, c.y);
        __half2 h3 = __floats2half2_rn(c.z, c.w);
        uint4 u;
        u.x = *(unsigned*)&h0; u.y = *(unsigned*)&h1;
        u.z = *(unsigned*)&h2; u.w = *(unsigned*)&h3;
        ((uint4*)g_x16)[i] = u;
    } else {
        if (b == cvtB && threadIdx.x < 128) g_sstat[threadIdx.x] = 0;
        int is64 = detect64(eb);
        int i = (b - cvtB) * blockDim.x + threadIdx.x;
        if (i >= e) return;
        int d = is64 ? eb[2 * (e + i)] : eb[e + i];
        atomicAdd(&g_cnt[d], 1);
    }
}

// ---------------- launch 2: single-pass scan (decoupled lookback) --------
// Computes rowptr (exclusive scan of cnt), cursor, dinv, resets cnt,
// sets rowptr[n]=e. nb <= 128 blocks, all resident -> no deadlock.
__global__ void __launch_bounds__(1024) k_scanF(int n, int e) {
    __shared__ int sh[1024];
    __shared__ int s_ex;
    int bid = blockIdx.x;
    int t = threadIdx.x;
    int gi = bid * 1024 + t;
    int v = (gi < n) ? g_cnt[gi] : 0;
    sh[t] = v;
    __syncthreads();
    for (int off = 1; off < 1024; off <<= 1) {
        int x = sh[t];
        int y = (t >= off) ? sh[t - off] : 0;
        __syncthreads();
        sh[t] = x + y;
        __syncthreads();
    }
    int incl = sh[t];
    int total = sh[1023];

    if (t == 0) {
        if (bid == 0) {
            g_spref[0] = total;
            __threadfence();
            g_sstat[0] = 2;
            s_ex = 0;
        } else {
            g_sagg[bid] = total;
            // lookback: poll predecessors (prefix-only protocol; statuses
            // flip to 2 in order, all blocks resident)
            int ex = 0;
            int j = bid - 1;
            while (true) {
                int s = g_sstat[j];
                if (s == 2) {
                    ex = g_spref[j];
                    break;
                }
            }
            g_spref[bid] = ex + total;
            __threadfence();
            g_sstat[bid] = 2;
            s_ex = ex;
        }
    }
    __syncthreads();
    int ex = s_ex;
    if (gi < n) {
        int rp = ex + incl - v;   // global exclusive
        g_rowptr[gi] = rp;
        g_cursor[gi] = rp;
        g_dinv[gi] = rsqrtf((float)(v + 1));
        g_cnt[gi] = 0;
    }
    if (bid == 0 && t == 0) g_rowptr[n] = e;
}

// ---------------- launch 3: CSR fill ----------------
__global__ void k_fill(const int* __restrict__ eb, int e) {
    int is64 = detect64(eb);
    int i = blockIdx.x * blockDim.x + threadIdx.x;
    if (i >= e) return;
    int s, d;
    if (is64) { s = eb[2 * i]; d = eb[2 * (e + i)]; }
    else      { s = eb[i];     d = eb[e + i]; }
    int p = atomicAdd(&g_cursor[d], 1);
    g_cedge[p] = make_int2(s, __float_as_int(g_dinv[s]));
}

// ---------------- aggregation: O[d] = dinv[d]*(sum_s dinv[s]*X[s] + dinv[d]*X[d])
__device__ __forceinline__ void acc8(float* a, uint4 u, float w) {
    float2 f;
    f = __half22float2(*(__half2*)&u.x); a[0] += w * f.x; a[1] += w * f.y;
    f = __half22float2(*(__half2*)&u.y); a[2] += w * f.x; a[3] += w * f.y;
    f = __half22float2(*(__half2*)&u.z); a[4] += w * f.x; a[5] += w * f.y;
    f = __half22float2(*(__half2*)&u.w); a[6] += w * f.x; a[7] += w * f.y;
}

__global__ void __launch_bounds__(256) k_agg16(
    const __half* __restrict__ H,
    __half* __restrict__ outh, int n0, int n1) {
    int node = n0 + ((blockIdx.x * blockDim.x + threadIdx.x) >> 5);
    int lane = threadIdx.x & 31;
    if (node >= n1) return;
    int p = lane >> 4, c = lane & 15;
    const uint4* H4 = (const uint4*)H;
    float di = g_dinv[node];

    float acc[8];
    {
        uint4 u = H4[(size_t)node * 16 + c];
        float w = (p == 0) ? di : 0.f;
        float2 f;
        f = __half22float2(*(__half2*)&u.x); acc[0] = w * f.x; acc[1] = w * f.y;
        f = __half22float2(*(__half2*)&u.y); acc[2] = w * f.x; acc[3] = w * f.y;
        f = __half22float2(*(__half2*)&u.z); acc[4] = w * f.x; acc[5] = w * f.y;
        f = __half22float2(*(__half2*)&u.w); acc[6] = w * f.x; acc[7] = w * f.y;
    }

    int beg = g_rowptr[node];
    int cnt = g_rowptr[node + 1] - beg;
    int done = 0;
    while (done < cnt) {
        int m = cnt - done;
        if (m > 32) m = 32;
        int idx = 0;
        float wv = 0.f;
        if (lane < m) {
            int2 ew = g_cedge[beg + done + lane];
            idx = ew.x;
            wv = __int_as_float(ew.y);
        }
        int j = 0;
        for (; j + 8 <= m; j += 8) {
            int i0 = __shfl_sync(FULLM, idx, j + p);
            float w0 = __shfl_sync(FULLM, wv, j + p);
            int i1 = __shfl_sync(FULLM, idx, j + 2 + p);
            float w1 = __shfl_sync(FULLM, wv, j + 2 + p);
            int i2 = __shfl_sync(FULLM, idx, j + 4 + p);
            float w2 = __shfl_sync(FULLM, wv, j + 4 + p);
            int i3 = __shfl_sync(FULLM, idx, j + 6 + p);
            float w3 = __shfl_sync(FULLM, wv, j + 6 + p);
            uint4 u0 = H4[(size_t)i0 * 16 + c];
            uint4 u1 = H4[(size_t)i1 * 16 + c];
            uint4 u2 = H4[(size_t)i2 * 16 + c];
            uint4 u3 = H4[(size_t)i3 * 16 + c];
            acc8(acc, u0, w0);
            acc8(acc, u1, w1);
            acc8(acc, u2, w2);
            acc8(acc, u3, w3);
        }
        for (; j + 2 <= m; j += 2) {
            int i0 = __shfl_sync(FULLM, idx, j + p);
            float w0 = __shfl_sync(FULLM, wv, j + p);
            uint4 u0 = H4[(size_t)i0 * 16 + c];
            acc8(acc, u0, w0);
        }
        if (j < m) {
            int i0 = __shfl_sync(FULLM, idx, j);
            float w0 = __shfl_sync(FULLM, wv, j);
            if (p == 0) {
                uint4 u0 = H4[(size_t)i0 * 16 + c];
                acc8(acc, u0, w0);
            }
        }
        done += m;
    }

#pragma unroll
    for (int k = 0; k < 8; k++)
        acc[k] += __shfl_xor_sync(FULLM, acc[k], 16);

    if (p == 0) {
        __half2 h0 = __floats2half2_rn(di * acc[0], di * acc[1]);
        __half2 h1 = __floats2half2_rn(di * acc[2], di * acc[3]);
        __half2 h2 = __floats2half2_rn(di * acc[4], di * acc[5]);
        __half2 h3 = __floats2half2_rn(di * acc[6], di * acc[7]);
        uint4 u;
        u.x = *(unsigned*)&h0; u.y = *(unsigned*)&h1;
        u.z = *(unsigned*)&h2; u.w = *(unsigned*)&h3;
        ((uint4*)outh)[(size_t)node * 16 + c] = u;
    }
}

// ---------------- GEMM + fused activation epilogue ----------------
__device__ __forceinline__ void mma_f16(float* d, const unsigned* a,
                                        unsigned b0, unsigned b1) {
    asm volatile(
        "mma.sync.aligned.m16n8k16.row.col.f32.f16.f16.f32 "
        "{%0,%1,%2,%3}, {%4,%5,%6,%7}, {%8,%9}, {%0,%1,%2,%3};\n"
        : "+f"(d[0]), "+f"(d[1]), "+f"(d[2]), "+f"(d[3])
        : "r"(a[0]), "r"(a[1]), "r"(a[2]), "r"(a[3]), "r"(b0), "r"(b1));
}

__global__ void __launch_bounds__(256) k_gemm(
    const __half* __restrict__ A, const float* __restrict__ W,
    const float* __restrict__ bias,
    __half* __restrict__ outh,                    // mode 0
    float* __restrict__ outf,                     // mode 1: emb
    const float* __restrict__ Wfc, const float* __restrict__ bfc,
    float* __restrict__ fcout,                    // mode 1: fc head
    int n0, int n, int mode) {
    extern __shared__ unsigned smu[];
    unsigned* Ahi = smu;
    unsigned* Bhi = Ahi + 128 * KP;
    unsigned* Blo = Bhi + 128 * KP;
    float* sfc = (float*)(Blo + 128 * KP);
    float* sWf = sfc + 128;
    float* sB  = sWf + 128;
    const int tid = threadIdx.x;
    const int row0 = n0 + blockIdx.x * 128;

    for (int i = tid; i < 8192; i += 256) {
        int nn_ = i & 127;
        int kp = i >> 7;
        int k = kp * 2;
        float w0 = W[k * DD + nn_];
        float w1 = W[(k + 1) * DD + nn_];
        __half h0 = __float2half_rn(w0), h1 = __float2half_rn(w1);
        __half2 hi = __halves2half2(h0, h1);
        __half2 lo = __floats2half2_rn(w0 - __half2float(h0),
                                       w1 - __half2float(h1));
        Bhi[nn_ * KP + kp] = *(unsigned*)&hi;
        Blo[nn_ * KP + kp] = *(unsigned*)&lo;
    }
    {
        const uint4* A4 = (const uint4*)A;
        for (int i = tid; i < 2048; i += 256) {
            int r = i >> 4, j = i & 15;
            uint4 u = make_uint4(0, 0, 0, 0);
            if (row0 + r < n) u = A4[(size_t)(row0 + r) * 16 + j];
            *(uint4*)(Ahi + r * KP + 4 * j) = u;
        }
    }
    if (tid < 128) {
        sB[tid] = bias[tid];
        sfc[tid] = 0.f;
        if (mode == 1) sWf[tid] = Wfc[tid];
    }
    __syncthreads();

    const int wid = tid >> 5, lane = tid & 31;
    const int grp = lane >> 2, tig = lane & 3;
    const int mrow0 = (wid >> 1) * 32;
    const int ncol0 = (wid & 1) * 64;

    float acc[2][8][4];
#pragma unroll
    for (int mi = 0; mi < 2; mi++)
#pragma unroll
        for (int ni = 0; ni < 8; ni++)
#pragma unroll
            for (int q = 0; q < 4; q++) acc[mi][ni][q] = 0.f;

#pragma unroll
    for (int ks = 0; ks < 8; ks++) {
        const int kw = ks * 8 + tig;
        unsigned ah[2][4];
#pragma unroll
        for (int mi = 0; mi < 2; mi++) {
            int r0 = mrow0 + mi * 16 + grp;
            ah[mi][0] = Ahi[r0 * KP + kw];
            ah[mi][1] = Ahi[(r0 + 8) * KP + kw];
            ah[mi][2] = Ahi[r0 * KP + kw + 4];
            ah[mi][3] = Ahi[(r0 + 8) * KP + kw + 4];
        }
#pragma unroll
        for (int ni = 0; ni < 8; ni++) {
            int nr = ncol0 + ni * 8 + grp;
            unsigned bh0 = Bhi[nr * KP + kw], bh1 = Bhi[nr * KP + kw + 4];
            unsigned bl0 = Blo[nr * KP + kw], bl1 = Blo[nr * KP + kw + 4];
#pragma unroll
            for (int mi = 0; mi < 2; mi++) {
                mma_f16(acc[mi][ni], ah[mi], bh0, bh1);
                mma_f16(acc[mi][ni], ah[mi], bl0, bl1);
            }
        }
    }

#pragma unroll
    for (int mi = 0; mi < 2; mi++) {
        int rA = row0 + mrow0 + mi * 16 + grp;
        float pA = 0.f, pB = 0.f;
#pragma unroll
        for (int ni = 0; ni < 8; ni++) {
            int ccol = ncol0 + ni * 8 + tig * 2;
            float bb0 = sB[ccol], bb1 = sB[ccol + 1];
            float v0 = tanhf(acc[mi][ni][0] + bb0);
            float v1 = tanhf(acc[mi][ni][1] + bb1);
            float v2 = tanhf(acc[mi][ni][2] + bb0);
            float v3 = tanhf(acc[mi][ni][3] + bb1);
            if (mode == 0) {
                if (rA < n)
                    *(__half2*)(outh + (size_t)rA * DD + ccol) =
                        __floats2half2_rn(v0, v1);
                if (rA + 8 < n)
                    *(__half2*)(outh + (size_t)(rA + 8) * DD + ccol) =
                        __floats2half2_rn(v2, v3);
            } else {
                if (rA < n)
                    *(float2*)(outf + (size_t)rA * DD + ccol) =
                        make_float2(v0, v1);
                if (rA + 8 < n)
                    *(float2*)(outf + (size_t)(rA + 8) * DD + ccol) =
                        make_float2(v2, v3);
                float wf0 = sWf[ccol], wf1 = sWf[ccol + 1];
                pA += v0 * wf0 + v1 * wf1;
                pB += v2 * wf0 + v3 * wf1;
            }
        }
        if (mode == 1) {
            int rl = mrow0 + mi * 16 + grp;
            if (rA < n) atomicAdd(&sfc[rl], pA);
            if (rA + 8 < n) atomicAdd(&sfc[rl + 8], pB);
        }
    }
    if (mode == 1) {
        __syncthreads();
        if (tid < 128) {
            int r = row0 + tid;
            if (r < n)
                fcout[r] = 1.0f / (1.0f + expf(-(sfc[tid] + bfc[0])));
        }
    }
}

// ---------------- launch ----------------
extern "C" void kernel_launch(void* const* d_in, const int* in_sizes, int n_in,
                              void* d_out, int out_size) {
    const float* x   = (const float*)d_in[0];
    const int*   eb  = (const int*)d_in[1];
    const float* W1  = (const float*)d_in[2];
    const float* b1  = (const float*)d_in[3];
    const float* W2  = (const float*)d_in[4];
    const float* b2  = (const float*)d_in[5];
    const float* Wfc = (const float*)d_in[6];
    const float* bfc = (const float*)d_in[7];

    int n = in_sizes[0] / DD;
    int e = in_sizes[1] / 2;

    float* out = (float*)d_out;
    float* emb = out + n;

    __half *px, *pa, *pf;
    cudaGetSymbolAddress((void**)&px, g_x16);
    cudaGetSymbolAddress((void**)&pa, g_ax);
    cudaGetSymbolAddress((void**)&pf, g_f16);

    static cudaStream_t s1 = nullptr, s2 = nullptr;
    static cudaEvent_t evF = nullptr, evP = nullptr, evG1 = nullptr,
                       evL = nullptr, evA[NCH], evB[NCH];
    static int init_done = 0;
    const int gemm_smem = (3 * 128 * KP + 384) * 4;
    if (!init_done) {
        cudaFuncSetAttribute(k_gemm,
                             cudaFuncAttributeMaxDynamicSharedMemorySize,
                             gemm_smem);
        cudaStreamCreateWithFlags(&s1, cudaStreamNonBlocking);
        cudaStreamCreateWithFlags(&s2, cudaStreamNonBlocking);
        cudaEventCreateWithFlags(&evF, cudaEventDisableTiming);
        cudaEventCreateWithFlags(&evP, cudaEventDisableTiming);
        cudaEventCreateWithFlags(&evG1, cudaEventDisableTiming);
        cudaEventCreateWithFlags(&evL, cudaEventDisableTiming);
        for (int c = 0; c < NCH; c++) {
            cudaEventCreateWithFlags(&evA[c], cudaEventDisableTiming);
            cudaEventCreateWithFlags(&evB[c], cudaEventDisableTiming);
        }
        init_done = 1;
    }

    const int T = 256;
    int total8 = n * 16;                    // 32B units of x
    int cvtB = (total8 + T - 1) / T;        // cvt blocks
    int histB = (e + T - 1) / T;            // hist blocks
    int nb = (n + 1023) / 1024;             // scan blocks (<=128)
    int chunk = (((n + NCH - 1) / NCH) + 127) & ~127;

    // preprocessing on s1: 3 launches, so agg chunk0 is submission #4
    cudaEventRecord(evF, 0);
    cudaStreamWaitEvent(s1, evF, 0);
    k_histcvt<<<cvtB + histB, T, 0, s1>>>(x, total8, eb, e, cvtB);   // 1
    k_scanF<<<nb, 1024, 0, s1>>>(n, e);                              // 2
    k_fill<<<histB, T, 0, s1>>>(eb, e);                              // 3
    cudaEventRecord(evP, s1);
    cudaStreamWaitEvent(0, evP, 0);

    // ---- layer 1: agg(x16) chunks pipelined with gemm1 ----
    for (int c = 0; c < NCH; c++) {
        int c0 = c * chunk, c1 = min(n, c0 + chunk);
        if (c0 >= n) break;
        int nodes = c1 - c0;
        k_agg16<<<(nodes * 32 + T - 1) / T, T>>>(px, pa, c0, c1);    // 4 = chunk0
        cudaEventRecord(evA[c], 0);
        cudaStreamWaitEvent(s2, evA[c], 0);
        k_gemm<<<(nodes + 127) / 128, 256, gemm_smem, s2>>>(
            pa, W1, b1, pf, nullptr, nullptr, nullptr, nullptr, c0, n, 0);
    }
    cudaEventRecord(evG1, s2);
    cudaStreamWaitEvent(0, evG1, 0);

    // ---- layer 2: agg(f) chunks pipelined with gemm2 (+emb, +fc head) ----
    for (int c = 0; c < NCH; c++) {
        int c0 = c * chunk, c1 = min(n, c0 + chunk);
        if (c0 >= n) break;
        int nodes = c1 - c0;
        k_agg16<<<(nodes * 32 + T - 1) / T, T>>>(pf, pa, c0, c1);
        cudaEventRecord(evB[c], 0);
        cudaStreamWaitEvent(s2, evB[c], 0);
        k_gemm<<<(nodes + 127) / 128, 256, gemm_smem, s2>>>(
            pa, W2, b2, nullptr, emb, Wfc, bfc, out, c0, n, 1);
    }
    cudaEventRecord(evL, s2);
    cudaStreamWaitEvent(0, evL, 0);
}

// round 16
// speedup vs baseline: 1.3877x; 1.3877x over previous
#include <cuda_runtime.h>
#include <cuda_fp16.h>
#include <math.h>
#include <stdint.h>

#define NN 100000
#define EE 1600000
#define DD 128
#define KP 68          // padded smem row stride in 32-bit words
#define NCH 4          // pipeline chunks
#define FULLM 0xFFFFFFFFu

// ---------------- device scratch (no allocations allowed) ----------------
__device__ int    g_rowptr[NN + 1];
__device__ int    g_cnt[NN];          // zero-init; re-zeroed by k_scanC
__device__ int    g_cursor[NN];
__device__ float  g_dinv[NN];
__device__ int    g_cesrc[EE];        // src ids, grouped by dst
__device__ int    g_bsums[128];
__device__ __half g_x16[(size_t)NN * DD];  // dinv-prescaled fp16 x
__device__ __half g_ax[(size_t)NN * DD];   // aggregated rows (both layers)
__device__ __half g_f16[(size_t)NN * DD];  // dinv-prescaled layer-1 acts

// ---------------- packed f32x2 helpers ----------------
__device__ __forceinline__ void addp(unsigned long long& a, float2 f) {
    unsigned long long b;
    asm("mov.b64 %0, {%1,%2};" : "=l"(b) : "f"(f.x), "f"(f.y));
    asm("add.rn.f32x2 %0, %0, %1;" : "+l"(a) : "l"(b));
}
__device__ __forceinline__ void accp(unsigned long long* a, uint4 u) {
    addp(a[0], __half22float2(*(__half2*)&u.x));
    addp(a[1], __half22float2(*(__half2*)&u.y));
    addp(a[2], __half22float2(*(__half2*)&u.z));
    addp(a[3], __half22float2(*(__half2*)&u.w));
}

// ---------------- x -> fp16, prescaled by dinv (needs dinv ready) --------
__global__ void k_cvt(const float* __restrict__ x, int total8) {
    int i = blockIdx.x * blockDim.x + threadIdx.x;
    if (i >= total8) return;
    float di = g_dinv[i >> 4];            // 16 x 8-float groups per row
    const float4* x4 = (const float4*)x;
    float4 a = x4[i * 2], b = x4[i * 2 + 1];
    __half2 h0 = __floats2half2_rn(di * a.x, di * a.y);
    __half2 h1 = __floats2half2_rn(di * a.z, di * a.w);
    __half2 h2 = __floats2half2_rn(di * b.x, di * b.y);
    __half2 h3 = __floats2half2_rn(di * b.z, di * b.w);
    uint4 u;
    u.x = *(unsigned*)&h0; u.y = *(unsigned*)&h1;
    u.z = *(unsigned*)&h2; u.w = *(unsigned*)&h3;
    ((uint4*)g_x16)[i] = u;
}

// ---------------- edge dtype detection (per warp) ----------------
__device__ __forceinline__ int detect64(const int* __restrict__ eb) {
    unsigned nz = 0;
#pragma unroll
    for (int i = (threadIdx.x & 31); i < 128; i += 32)
        nz |= (eb[2 * i + 1] != 0);
    return __ballot_sync(FULLM, nz) == 0;
}

// ---------------- preprocessing (R7 formulation) ----------------
__global__ void k_hist(const int* __restrict__ eb, int e) {
    int is64 = detect64(eb);
    int i = blockIdx.x * blockDim.x + threadIdx.x;
    if (i >= e) return;
    int d = is64 ? eb[2 * (e + i)] : eb[e + i];
    atomicAdd(&g_cnt[d], 1);
}

__global__ void k_scanA(int n) {
    __shared__ int sh[1024];
    int gi = blockIdx.x * 1024 + threadIdx.x;
    int v = (gi < n) ? g_cnt[gi] : 0;
    sh[threadIdx.x] = v;
    __syncthreads();
    for (int off = 1; off < 1024; off <<= 1) {
        int x = sh[threadIdx.x];
        int y = (threadIdx.x >= off) ? sh[threadIdx.x - off] : 0;
        __syncthreads();
        sh[threadIdx.x] = x + y;
        __syncthreads();
    }
    int incl = sh[threadIdx.x];
    if (gi < n) g_rowptr[gi] = incl - v;
    if (threadIdx.x == 1023) g_bsums[blockIdx.x] = incl;
}

__global__ void k_scanC(int n, int e) {
    __shared__ int sh[128];
    int t = threadIdx.x;
    int nb = (n + 1023) >> 10;
    if (t < 128) sh[t] = (t < nb) ? g_bsums[t] : 0;
    __syncthreads();
    for (int off = 1; off < 128; off <<= 1) {
        int x = 0, y = 0;
        if (t < 128) { x = sh[t]; y = (t >= off) ? sh[t - off] : 0; }
        __syncthreads();
        if (t < 128) sh[t] = x + y;
        __syncthreads();
    }
    int i = blockIdx.x * blockDim.x + t;
    if (i < n) {
        int blk = i >> 10;
        int ex = blk ? sh[blk - 1] : 0;
        int rp = g_rowptr[i] + ex;
        g_rowptr[i] = rp;
        g_cursor[i] = rp;
        g_dinv[i] = rsqrtf((float)(g_cnt[i] + 1));
        g_cnt[i] = 0;
    }
    if (blockIdx.x == 0 && t == 0) g_rowptr[n] = e;
}

__global__ void k_fill(const int* __restrict__ eb, int e) {
    int is64 = detect64(eb);
    int i = blockIdx.x * blockDim.x + threadIdx.x;
    if (i >= e) return;
    int s, d;
    if (is64) { s = eb[2 * i]; d = eb[2 * (e + i)]; }
    else      { s = eb[i];     d = eb[e + i]; }
    int p = atomicAdd(&g_cursor[d], 1);
    g_cesrc[p] = s;
}

// ---------------- aggregation: O[d] = dinv[d]*(sum_s X'[s] + X'[d]) ------
// X' rows are dinv-prescaled -> no per-edge weight. One warp per node,
// 2 edge-slots x 16 lanes, packed f32x2 accumulation.
__global__ void __launch_bounds__(256) k_agg16(
    const __half* __restrict__ H,
    __half* __restrict__ outh, int n0, int n1) {
    int node = n0 + ((blockIdx.x * blockDim.x + threadIdx.x) >> 5);
    int lane = threadIdx.x & 31;
    if (node >= n1) return;
    int p = lane >> 4, c = lane & 15;
    const uint4* H4 = (const uint4*)H;
    float di = g_dinv[node];

    unsigned long long acc[4] = {0ull, 0ull, 0ull, 0ull};
    if (p == 0) {
        uint4 u = H4[(size_t)node * 16 + c];   // self term (prescaled)
        accp(acc, u);
    }

    int beg = g_rowptr[node];
    int cnt = g_rowptr[node + 1] - beg;
    int done = 0;
    while (done < cnt) {
        int m = cnt - done;
        if (m > 32) m = 32;
        int idx = (lane < m) ? g_cesrc[beg + done + lane] : 0;
        int j = 0;
        for (; j + 8 <= m; j += 8) {
            int i0 = __shfl_sync(FULLM, idx, j + p);
            int i1 = __shfl_sync(FULLM, idx, j + 2 + p);
            int i2 = __shfl_sync(FULLM, idx, j + 4 + p);
            int i3 = __shfl_sync(FULLM, idx, j + 6 + p);
            uint4 u0 = H4[(size_t)i0 * 16 + c];
            uint4 u1 = H4[(size_t)i1 * 16 + c];
            uint4 u2 = H4[(size_t)i2 * 16 + c];
            uint4 u3 = H4[(size_t)i3 * 16 + c];
            accp(acc, u0);
            accp(acc, u1);
            accp(acc, u2);
            accp(acc, u3);
        }
        for (; j + 2 <= m; j += 2) {
            int i0 = __shfl_sync(FULLM, idx, j + p);
            uint4 u0 = H4[(size_t)i0 * 16 + c];
            accp(acc, u0);
        }
        if (j < m) {
            int i0 = __shfl_sync(FULLM, idx, j);
            if (p == 0) {
                uint4 u0 = H4[(size_t)i0 * 16 + c];
                accp(acc, u0);
            }
        }
        done += m;
    }

    float res[8];
#pragma unroll
    for (int k = 0; k < 4; k++) {
        float2 f;
        asm("mov.b64 {%0,%1}, %2;" : "=f"(f.x), "=f"(f.y) : "l"(acc[k]));
        res[2 * k] = f.x;
        res[2 * k + 1] = f.y;
    }
#pragma unroll
    for (int k = 0; k < 8; k++)
        res[k] += __shfl_xor_sync(FULLM, res[k], 16);

    if (p == 0) {
        __half2 h0 = __floats2half2_rn(di * res[0], di * res[1]);
        __half2 h1 = __floats2half2_rn(di * res[2], di * res[3]);
        __half2 h2 = __floats2half2_rn(di * res[4], di * res[5]);
        __half2 h3 = __floats2half2_rn(di * res[6], di * res[7]);
        uint4 u;
        u.x = *(unsigned*)&h0; u.y = *(unsigned*)&h1;
        u.z = *(unsigned*)&h2; u.w = *(unsigned*)&h3;
        ((uint4*)outh)[(size_t)node * 16 + c] = u;
    }
}

// ---------------- GEMM + fused activation epilogue ----------------
__device__ __forceinline__ void mma_f16(float* d, const unsigned* a,
                                        unsigned b0, unsigned b1) {
    asm volatile(
        "mma.sync.aligned.m16n8k16.row.col.f32.f16.f16.f32 "
        "{%0,%1,%2,%3}, {%4,%5,%6,%7}, {%8,%9}, {%0,%1,%2,%3};\n"
        : "+f"(d[0]), "+f"(d[1]), "+f"(d[2]), "+f"(d[3])
        : "r"(a[0]), "r"(a[1]), "r"(a[2]), "r"(a[3]), "r"(b0), "r"(b1));
}

// mode 0: f' = dinv[r] * tanh(A@W + b)  (fp16, prescaled for next agg)
// mode 1: emb = tanh(A@W + b) (fp32) + fused sigmoid FC head
__global__ void __launch_bounds__(256) k_gemm(
    const __half* __restrict__ A, const float* __restrict__ W,
    const float* __restrict__ bias,
    __half* __restrict__ outh,
    float* __restrict__ outf,
    const float* __restrict__ Wfc, const float* __restrict__ bfc,
    float* __restrict__ fcout,
    int n0, int n, int mode) {
    extern __shared__ unsigned smu[];
    unsigned* Ahi = smu;
    unsigned* Bhi = Ahi + 128 * KP;
    unsigned* Blo = Bhi + 128 * KP;
    float* sfc = (float*)(Blo + 128 * KP);
    float* sWf = sfc + 128;
    float* sB  = sWf + 128;
    const int tid = threadIdx.x;
    const int row0 = n0 + blockIdx.x * 128;

    for (int i = tid; i < 8192; i += 256) {
        int nn_ = i & 127;
        int kp = i >> 7;
        int k = kp * 2;
        float w0 = W[k * DD + nn_];
        float w1 = W[(k + 1) * DD + nn_];
        __half h0 = __float2half_rn(w0), h1 = __float2half_rn(w1);
        __half2 hi = __halves2half2(h0, h1);
        __half2 lo = __floats2half2_rn(w0 - __half2float(h0),
                                       w1 - __half2float(h1));
        Bhi[nn_ * KP + kp] = *(unsigned*)&hi;
        Blo[nn_ * KP + kp] = *(unsigned*)&lo;
    }
    {
        const uint4* A4 = (const uint4*)A;
        for (int i = tid; i < 2048; i += 256) {
            int r = i >> 4, j = i & 15;
            uint4 u = make_uint4(0, 0, 0, 0);
            if (row0 + r < n) u = A4[(size_t)(row0 + r) * 16 + j];
            *(uint4*)(Ahi + r * KP + 4 * j) = u;
        }
    }
    if (tid < 128) {
        sB[tid] = bias[tid];
        sfc[tid] = 0.f;
        if (mode == 1) sWf[tid] = Wfc[tid];
    }
    __syncthreads();

    const int wid = tid >> 5, lane = tid & 31;
    const int grp = lane >> 2, tig = lane & 3;
    const int mrow0 = (wid >> 1) * 32;
    const int ncol0 = (wid & 1) * 64;

    float acc[2][8][4];
#pragma unroll
    for (int mi = 0; mi < 2; mi++)
#pragma unroll
        for (int ni = 0; ni < 8; ni++)
#pragma unroll
            for (int q = 0; q < 4; q++) acc[mi][ni][q] = 0.f;

#pragma unroll
    for (int ks = 0; ks < 8; ks++) {
        const int kw = ks * 8 + tig;
        unsigned ah[2][4];
#pragma unroll
        for (int mi = 0; mi < 2; mi++) {
            int r0 = mrow0 + mi * 16 + grp;
            ah[mi][0] = Ahi[r0 * KP + kw];
            ah[mi][1] = Ahi[(r0 + 8) * KP + kw];
            ah[mi][2] = Ahi[r0 * KP + kw + 4];
            ah[mi][3] = Ahi[(r0 + 8) * KP + kw + 4];
        }
#pragma unroll
        for (int ni = 0; ni < 8; ni++) {
            int nr = ncol0 + ni * 8 + grp;
            unsigned bh0 = Bhi[nr * KP + kw], bh1 = Bhi[nr * KP + kw + 4];
            unsigned bl0 = Blo[nr * KP + kw], bl1 = Blo[nr * KP + kw + 4];
#pragma unroll
            for (int mi = 0; mi < 2; mi++) {
                mma_f16(acc[mi][ni], ah[mi], bh0, bh1);
                mma_f16(acc[mi][ni], ah[mi], bl0, bl1);
            }
        }
    }

#pragma unroll
    for (int mi = 0; mi < 2; mi++) {
        int rA = row0 + mrow0 + mi * 16 + grp;
        float dA = 1.f, dB = 1.f;
        if (mode == 0) {
            dA = (rA < n) ? g_dinv[rA] : 0.f;
            dB = (rA + 8 < n) ? g_dinv[rA + 8] : 0.f;
        }
        float pA = 0.f, pB = 0.f;
#pragma unroll
        for (int ni = 0; ni < 8; ni++) {
            int ccol = ncol0 + ni * 8 + tig * 2;
            float bb0 = sB[ccol], bb1 = sB[ccol + 1];
            float v0 = tanhf(acc[mi][ni][0] + bb0);
            float v1 = tanhf(acc[mi][ni][1] + bb1);
            float v2 = tanhf(acc[mi][ni][2] + bb0);
            float v3 = tanhf(acc[mi][ni][3] + bb1);
            if (mode == 0) {
                if (rA < n)
                    *(__half2*)(outh + (size_t)rA * DD + ccol) =
                        __floats2half2_rn(dA * v0, dA * v1);
                if (rA + 8 < n)
                    *(__half2*)(outh + (size_t)(rA + 8) * DD + ccol) =
                        __floats2half2_rn(dB * v2, dB * v3);
            } else {
                if (rA < n)
                    *(float2*)(outf + (size_t)rA * DD + ccol) =
                        make_float2(v0, v1);
                if (rA + 8 < n)
                    *(float2*)(outf + (size_t)(rA + 8) * DD + ccol) =
                        make_float2(v2, v3);
                float wf0 = sWf[ccol], wf1 = sWf[ccol + 1];
                pA += v0 * wf0 + v1 * wf1;
                pB += v2 * wf0 + v3 * wf1;
            }
        }
        if (mode == 1) {
            int rl = mrow0 + mi * 16 + grp;
            if (rA < n) atomicAdd(&sfc[rl], pA);
            if (rA + 8 < n) atomicAdd(&sfc[rl + 8], pB);
        }
    }
    if (mode == 1) {
        __syncthreads();
        if (tid < 128) {
            int r = row0 + tid;
            if (r < n)
                fcout[r] = 1.0f / (1.0f + expf(-(sfc[tid] + bfc[0])));
        }
    }
}

// ---------------- launch ----------------
extern "C" void kernel_launch(void* const* d_in, const int* in_sizes, int n_in,
                              void* d_out, int out_size) {
    const float* x   = (const float*)d_in[0];
    const int*   eb  = (const int*)d_in[1];
    const float* W1  = (const float*)d_in[2];
    const float* b1  = (const float*)d_in[3];
    const float* W2  = (const float*)d_in[4];
    const float* b2  = (const float*)d_in[5];
    const float* Wfc = (const float*)d_in[6];
    const float* bfc = (const float*)d_in[7];

    int n = in_sizes[0] / DD;
    int e = in_sizes[1] / 2;

    float* out = (float*)d_out;
    float* emb = out + n;

    __half *px, *pa, *pf;
    cudaGetSymbolAddress((void**)&px, g_x16);
    cudaGetSymbolAddress((void**)&pa, g_ax);
    cudaGetSymbolAddress((void**)&pf, g_f16);

    static cudaStream_t s1 = nullptr, s2 = nullptr;
    static cudaEvent_t evF = nullptr, evD = nullptr, evP = nullptr,
                       evG1 = nullptr, evL = nullptr, evA[NCH], evB[NCH];
    static int init_done = 0;
    const int gemm_smem = (3 * 128 * KP + 384) * 4;
    if (!init_done) {
        cudaFuncSetAttribute(k_gemm,
                             cudaFuncAttributeMaxDynamicSharedMemorySize,
                             gemm_smem);
        cudaStreamCreateWithFlags(&s1, cudaStreamNonBlocking);
        cudaStreamCreateWithFlags(&s2, cudaStreamNonBlocking);
        cudaEventCreateWithFlags(&evF, cudaEventDisableTiming);
        cudaEventCreateWithFlags(&evD, cudaEventDisableTiming);
        cudaEventCreateWithFlags(&evP, cudaEventDisableTiming);
        cudaEventCreateWithFlags(&evG1, cudaEventDisableTiming);
        cudaEventCreateWithFlags(&evL, cudaEventDisableTiming);
        for (int c = 0; c < NCH; c++) {
            cudaEventCreateWithFlags(&evA[c], cudaEventDisableTiming);
            cudaEventCreateWithFlags(&evB[c], cudaEventDisableTiming);
        }
        init_done = 1;
    }

    const int T = 256;
    int nb = (n + 1023) / 1024;
    int chunk = (((n + NCH - 1) / NCH) + 127) & ~127;

    // fork preprocessing onto s1
    cudaEventRecord(evF, 0);
    cudaStreamWaitEvent(s1, evF, 0);
    k_hist<<<(e + T - 1) / T, T, 0, s1>>>(eb, e);
    k_scanA<<<nb, 1024, 0, s1>>>(n);
    k_scanC<<<(n + T - 1) / T, T, 0, s1>>>(n, e);
    cudaEventRecord(evD, s1);                      // dinv ready
    k_fill<<<(e + T - 1) / T, T, 0, s1>>>(eb, e);
    cudaEventRecord(evP, s1);

    // cvt needs dinv -> runs on s0 after scanC, parallel with fill
    cudaStreamWaitEvent(0, evD, 0);
    k_cvt<<<(n * 16 + T - 1) / T, T>>>(x, n * 16);
    cudaStreamWaitEvent(0, evP, 0);

    // ---- layer 1: agg(x') chunks pipelined with gemm1 ----
    for (int c = 0; c < NCH; c++) {
        int c0 = c * chunk, c1 = min(n, c0 + chunk);
        if (c0 >= n) break;
        int nodes = c1 - c0;
        k_agg16<<<(nodes * 32 + T - 1) / T, T>>>(px, pa, c0, c1);
        cudaEventRecord(evA[c], 0);
        cudaStreamWaitEvent(s2, evA[c], 0);
        k_gemm<<<(nodes + 127) / 128, 256, gemm_smem, s2>>>(
            pa, W1, b1, pf, nullptr, nullptr, nullptr, nullptr, c0, n, 0);
    }
    cudaEventRecord(evG1, s2);
    cudaStreamWaitEvent(0, evG1, 0);

    // ---- layer 2: agg(f') chunks pipelined with gemm2 (+emb, +fc head) ----
    for (int c = 0; c < NCH; c++) {
        int c0 = c * chunk, c1 = min(n, c0 + chunk);
        if (c0 >= n) break;
        int nodes = c1 - c0;
        k_agg16<<<(nodes * 32 + T - 1) / T, T>>>(pf, pa, c0, c1);
        cudaEventRecord(evB[c], 0);
        cudaStreamWaitEvent(s2, evB[c], 0);
        k_gemm<<<(nodes + 127) / 128, 256, gemm_smem, s2>>>(
            pa, W2, b2, nullptr, emb, Wfc, bfc, out, c0, n, 1);
    }
    cudaEventRecord(evL, s2);
    cudaStreamWaitEvent(0, evL, 0);
}